// round 9
// baseline (speedup 1.0000x reference)
#include <cuda_runtime.h>
#include <cuda.h>
#include <cuda_fp16.h>
#include <cstdint>

// ================================================================
// out[8192,4096] = A[8192,4096] (K-major) * W[4096,4096] (K-major)^T
// fp16 mma.sync m16n8k16 + ldmatrix + TMA (SW128), 4-stage
// producer/consumer mbarrier pipeline, CTA 128x256, warp 64x64,
// fragment double-buffering across ks + early empty-arrive.
// ================================================================

#define M_DIM 8192
#define N_DIM 4096
#define K_DIM 4096

#define BM 128
#define BN 256
#define BK 64                        // fp16 per K chunk = 128 B/row
#define STAGES 4
#define NCHUNK (K_DIM / BK)          // 64
#define NWARPS 8

#define A_STAGE_BYTES (BM * 128)     // 16384
#define B_STAGE_BYTES (BN * 128)     // 32768
#define STAGE_BYTES   (A_STAGE_BYTES + B_STAGE_BYTES)      // 49152
#define SMEM_TILE_OFF 1024
#define SMEM_BYTES    (SMEM_TILE_OFF + STAGES * STAGE_BYTES)  // 197632

__device__ __align__(1024) __half g_A[(size_t)M_DIM * K_DIM];
__device__ __align__(1024) __half g_B[(size_t)N_DIM * K_DIM];

__device__ __forceinline__ uint32_t smem_u32(const void* p) {
    uint32_t a;
    asm("{ .reg .u64 t; cvta.to.shared.u64 t, %1; cvt.u32.u64 %0, t; }" : "=r"(a) : "l"(p));
    return a;
}
#define MBARRIER_INIT(a, n) \
    asm volatile("mbarrier.init.shared.b64 [%0], %1;" :: "r"((uint32_t)(a)), "r"((uint32_t)(n)) : "memory")
#define MBARRIER_EXPECT_TX(a, b) \
    asm volatile("mbarrier.arrive.expect_tx.shared.b64 _, [%0], %1;" :: "r"((uint32_t)(a)), "r"((uint32_t)(b)) : "memory")
#define MBARRIER_ARRIVE(a) \
    asm volatile("mbarrier.arrive.shared.b64 _, [%0];" :: "r"((uint32_t)(a)) : "memory")

#define MBARRIER_WAIT_ACQ(a, ph) do {                                               \
    uint32_t _m = (uint32_t)(a), _p = (uint32_t)(ph), _d;                           \
    asm volatile("{\n\t.reg .pred p;\n\t"                                           \
        "mbarrier.try_wait.parity.acquire.cta.shared::cta.b64 p, [%1], %2;\n\t"     \
        "selp.b32 %0, 1, 0, p;\n\t}" : "=r"(_d) : "r"(_m), "r"(_p) : "memory");     \
    if (!_d) {                                                                       \
        asm volatile("{\n\t.reg .pred P1;\n\t"                                      \
            "WL_%=:\n\t"                                                            \
            "mbarrier.try_wait.parity.acquire.cta.shared::cta.b64 P1, [%0], %1, 0x989680;\n\t" \
            "@P1 bra.uni WD_%=;\n\t bra.uni WL_%=;\n\t WD_%=:\n\t}"                 \
            :: "r"(_m), "r"(_p) : "memory");                                        \
    }                                                                                \
} while (0)

#define MBARRIER_WAIT_RLX(a, ph) do {                                               \
    uint32_t _m = (uint32_t)(a), _p = (uint32_t)(ph), _d;                           \
    asm volatile("{\n\t.reg .pred p;\n\t"                                           \
        "mbarrier.try_wait.parity.relaxed.cta.shared::cta.b64 p, [%1], %2, 0x989680;\n\t" \
        "selp.b32 %0, 1, 0, p;\n\t}" : "=r"(_d) : "r"(_m), "r"(_p) : "memory");     \
    if (!_d) {                                                                       \
        asm volatile("{\n\t.reg .pred P1;\n\t"                                      \
            "WL_%=:\n\t"                                                            \
            "mbarrier.try_wait.parity.relaxed.cta.shared::cta.b64 P1, [%0], %1, 0x989680;\n\t" \
            "@P1 bra.uni WD_%=;\n\t bra.uni WL_%=;\n\t WD_%=:\n\t}"                 \
            :: "r"(_m), "r"(_p) : "memory");                                        \
    }                                                                                \
} while (0)

#define TMA_LOAD_2D(smem, map, c0, c1, mbar)                                        \
    asm volatile("cp.async.bulk.tensor.2d.shared::cta.global.tile.mbarrier::complete_tx::bytes " \
        "[%0], [%1, {%2, %3}], [%4];"                                               \
        :: "r"((uint32_t)(smem)), "l"(map), "r"((int)(c0)), "r"((int)(c1)),         \
           "r"((uint32_t)(mbar)) : "memory")

__device__ __forceinline__ void ldsm_x4(uint32_t r[4], uint32_t addr) {
    asm volatile("ldmatrix.sync.aligned.m8n8.x4.shared.b16 {%0,%1,%2,%3}, [%4];"
                 : "=r"(r[0]), "=r"(r[1]), "=r"(r[2]), "=r"(r[3]) : "r"(addr));
}
__device__ __forceinline__ void mma_f16(float c[4], const uint32_t a[4],
                                        uint32_t b0, uint32_t b1) {
    asm volatile(
        "mma.sync.aligned.m16n8k16.row.col.f32.f16.f16.f32 "
        "{%0,%1,%2,%3}, {%4,%5,%6,%7}, {%8,%9}, {%0,%1,%2,%3};"
        : "+f"(c[0]), "+f"(c[1]), "+f"(c[2]), "+f"(c[3])
        : "r"(a[0]), "r"(a[1]), "r"(a[2]), "r"(a[3]), "r"(b0), "r"(b1));
}

__global__ void __launch_bounds__(256) cvt_f16_kernel(
    const float4* __restrict__ in, __half2* __restrict__ out, int n4)
{
    int stride = gridDim.x * blockDim.x;
    for (int i = blockIdx.x * blockDim.x + threadIdx.x; i < n4; i += stride) {
        float4 v = in[i];
        out[2 * i]     = __floats2half2_rn(v.x, v.y);
        out[2 * i + 1] = __floats2half2_rn(v.z, v.w);
    }
}

extern __shared__ char smemc[];

// smem barriers: full[s] = sb + 16*s, empty[s] = sb + 16*s + 8
__global__ void __launch_bounds__(256, 1) agg_gemm_kernel(
    const __grid_constant__ CUtensorMap tma_a,
    const __grid_constant__ CUtensorMap tma_b,
    float* __restrict__ out)
{
    const int t = threadIdx.x;
    const int wid = t >> 5;
    const int lane = t & 31;
    const int wm = wid & 1;          // warp M (0..1): 64 rows
    const int wn = wid >> 1;         // warp N (0..3): 64 cols
    const int g = lane >> 2;
    const int tig = lane & 3;

    const int m0 = blockIdx.y * BM;
    const int n0 = blockIdx.x * BN;

    const uint32_t sb = smem_u32(smemc);
    const uint32_t tiles = sb + SMEM_TILE_OFF;

    if (t == 0) {
        #pragma unroll
        for (int s = 0; s < STAGES; s++) {
            MBARRIER_INIT(sb + 16 * s, 1);           // full: tx-based
            MBARRIER_INIT(sb + 16 * s + 8, NWARPS);  // empty: 8 warp arrives
        }
    }
    __syncthreads();

    int pstage = 0, pphase = 1;      // producer cursor
    auto produce = [&](int chunk) {
        const uint32_t fullb = sb + 16 * pstage;
        MBARRIER_WAIT_RLX(fullb + 8, pphase);
        MBARRIER_EXPECT_TX(fullb, STAGE_BYTES);
        const uint32_t sbase = tiles + (uint32_t)pstage * STAGE_BYTES;
        TMA_LOAD_2D(sbase,                 &tma_a, chunk * BK, m0, fullb);
        TMA_LOAD_2D(sbase + A_STAGE_BYTES, &tma_b, chunk * BK, n0, fullb);
        if (++pstage == STAGES) { pstage = 0; pphase ^= 1; }
    };

    if (t == 0) {
        #pragma unroll
        for (int ps = 0; ps < STAGES - 1; ps++) produce(ps);
    }

    float acc[4][8][4];
    #pragma unroll
    for (int mi = 0; mi < 4; mi++)
        #pragma unroll
        for (int ni = 0; ni < 8; ni++)
            #pragma unroll
            for (int q = 0; q < 4; q++) acc[mi][ni][q] = 0.0f;

    // ldmatrix: row = base + (lane&15); chunk16 ^= (row & 7)
    const int lrow = lane & 15;
    const int lhi = lane >> 4;
    const int lsw = lane & 7;
    const uint32_t a_row_off = (uint32_t)(wm * 64 + lrow) * 128u;
    const uint32_t b_row_off = (uint32_t)A_STAGE_BYTES + (uint32_t)(wn * 64 + lrow) * 128u;

    int cstage = 0, cphase = 0;

    uint32_t abuf[2][4][4], bbuf[2][4][4];

    auto load_frags = [&](int buf, uint32_t sbase, int ks) {
        const uint32_t chunk = (uint32_t)(((ks * 2 + lhi) ^ lsw) * 16);
        #pragma unroll
        for (int mi = 0; mi < 4; mi++)
            ldsm_x4(abuf[buf][mi], sbase + a_row_off + (uint32_t)(mi * 16 * 128) + chunk);
        #pragma unroll
        for (int p = 0; p < 4; p++)
            ldsm_x4(bbuf[buf][p], sbase + b_row_off + (uint32_t)(p * 16 * 128) + chunk);
    };
    auto do_mmas = [&](int buf) {
        #pragma unroll
        for (int mi = 0; mi < 4; mi++) {
            #pragma unroll
            for (int p = 0; p < 4; p++) {
                mma_f16(acc[mi][2 * p],     abuf[buf][mi], bbuf[buf][p][0], bbuf[buf][p][2]);
                mma_f16(acc[mi][2 * p + 1], abuf[buf][mi], bbuf[buf][p][1], bbuf[buf][p][3]);
            }
        }
    };

    for (int c = 0; c < NCHUNK; c++) {
        const int fetch = c + STAGES - 1;
        if (t == 0 && fetch < NCHUNK) produce(fetch);

        const uint32_t fullb = sb + 16 * cstage;
        MBARRIER_WAIT_ACQ(fullb, cphase);

        const uint32_t sbase = tiles + (uint32_t)cstage * STAGE_BYTES;

        // software-pipelined fragments: load ks+1 while computing ks
        load_frags(0, sbase, 0);
        load_frags(1, sbase, 1);
        do_mmas(0);
        load_frags(0, sbase, 2);
        do_mmas(1);
        load_frags(1, sbase, 3);
        // last read of the stage done -> release it early (overlaps MMA tail)
        if (lane == 0) MBARRIER_ARRIVE(fullb + 8);
        do_mmas(0);
        do_mmas(1);

        if (++cstage == STAGES) { cstage = 0; cphase ^= 1; }
    }

    // ---------------- epilogue ----------------
    #pragma unroll
    for (int mi = 0; mi < 4; mi++) {
        const int row = m0 + wm * 64 + mi * 16 + g;
        #pragma unroll
        for (int ni = 0; ni < 8; ni++) {
            const int col = n0 + wn * 64 + ni * 8 + 2 * tig;
            float2 lo = make_float2(acc[mi][ni][0], acc[mi][ni][1]);
            float2 hi = make_float2(acc[mi][ni][2], acc[mi][ni][3]);
            *reinterpret_cast<float2*>(out + (size_t)row * N_DIM + col) = lo;
            *reinterpret_cast<float2*>(out + (size_t)(row + 8) * N_DIM + col) = hi;
        }
    }
}

// ---------------- host ----------------
typedef CUresult (*PFN_EncodeTiled)(
    CUtensorMap*, CUtensorMapDataType, cuuint32_t, void*,
    const cuuint64_t*, const cuuint64_t*, const cuuint32_t*, const cuuint32_t*,
    CUtensorMapInterleave, CUtensorMapSwizzle, CUtensorMapL2promotion, CUtensorMapFloatOOBfill);

static void encode_2d_f16(PFN_EncodeTiled enc, CUtensorMap* map, void* ptr,
                          uint64_t dim0, uint64_t dim1, uint32_t box0, uint32_t box1) {
    cuuint64_t dims[2]    = {dim0, dim1};
    cuuint64_t strides[1] = {dim0 * sizeof(__half)};
    cuuint32_t box[2]     = {box0, box1};
    cuuint32_t estr[2]    = {1, 1};
    enc(map, CU_TENSOR_MAP_DATA_TYPE_FLOAT16, 2, ptr, dims, strides, box, estr,
        CU_TENSOR_MAP_INTERLEAVE_NONE, CU_TENSOR_MAP_SWIZZLE_128B,
        CU_TENSOR_MAP_L2_PROMOTION_L2_128B, CU_TENSOR_MAP_FLOAT_OOB_FILL_NONE);
}

extern "C" void kernel_launch(void* const* d_in, const int* in_sizes, int n_in,
                              void* d_out, int out_size) {
    const float* A_in = (const float*)d_in[0];   // [8,1024,4096] = [8192,4096]
    const float* W_in = (const float*)d_in[1];   // [4096,4096] K-major
    float* out = (float*)d_out;

    void *pA = nullptr, *pB = nullptr;
    cudaGetSymbolAddress(&pA, g_A);
    cudaGetSymbolAddress(&pB, g_B);

    void* fn = nullptr;
    cudaDriverEntryPointQueryResult st;
    cudaGetDriverEntryPointByVersion("cuTensorMapEncodeTiled", &fn, 12000,
                                     cudaEnableDefault, &st);
    PFN_EncodeTiled enc = (PFN_EncodeTiled)fn;

    CUtensorMap mapA, mapB;
    encode_2d_f16(enc, &mapA, pA, K_DIM, M_DIM, BK, BM);
    encode_2d_f16(enc, &mapB, pB, K_DIM, N_DIM, BK, BN);

    cudaFuncSetAttribute(agg_gemm_kernel,
                         cudaFuncAttributeMaxDynamicSharedMemorySize, SMEM_BYTES);

    cvt_f16_kernel<<<1184, 256>>>((const float4*)A_in, (__half2*)pA,
                                  (int)(((size_t)M_DIM * K_DIM) / 4));
    cvt_f16_kernel<<<1184, 256>>>((const float4*)W_in, (__half2*)pB,
                                  (int)(((size_t)N_DIM * K_DIM) / 4));

    dim3 grid(N_DIM / BN, M_DIM / BM);   // (16, 64)
    agg_gemm_kernel<<<grid, 256, SMEM_BYTES>>>(mapA, mapB, out);
}

// round 10
// speedup vs baseline: 1.0454x; 1.0454x over previous
#include <cuda_runtime.h>
#include <cuda.h>
#include <cuda_fp16.h>
#include <cstdint>

// ================================================================
// out[8192,4096] = A[8192,4096] (K-major) * W[4096,4096] (K-major)^T
// fp16 mma.sync m16n8k16 + ldmatrix + TMA (SW128), 4-stage
// producer/consumer mbarrier pipeline. CTA 128x256, 512 threads,
// 16 warps (warp tile 32x64) -> 4 warps/SMSP for latency hiding.
// ================================================================

#define M_DIM 8192
#define N_DIM 4096
#define K_DIM 4096

#define BM 128
#define BN 256
#define BK 64                        // fp16 per K chunk = 128 B/row
#define STAGES 4
#define NCHUNK (K_DIM / BK)          // 64
#define NTHREADS 512
#define NWARPS 16

#define A_STAGE_BYTES (BM * 128)     // 16384
#define B_STAGE_BYTES (BN * 128)     // 32768
#define STAGE_BYTES   (A_STAGE_BYTES + B_STAGE_BYTES)      // 49152
#define SMEM_TILE_OFF 1024
#define SMEM_BYTES    (SMEM_TILE_OFF + STAGES * STAGE_BYTES)  // 197632

__device__ __align__(1024) __half g_A[(size_t)M_DIM * K_DIM];
__device__ __align__(1024) __half g_B[(size_t)N_DIM * K_DIM];

__device__ __forceinline__ uint32_t smem_u32(const void* p) {
    uint32_t a;
    asm("{ .reg .u64 t; cvta.to.shared.u64 t, %1; cvt.u32.u64 %0, t; }" : "=r"(a) : "l"(p));
    return a;
}
#define MBARRIER_INIT(a, n) \
    asm volatile("mbarrier.init.shared.b64 [%0], %1;" :: "r"((uint32_t)(a)), "r"((uint32_t)(n)) : "memory")
#define MBARRIER_EXPECT_TX(a, b) \
    asm volatile("mbarrier.arrive.expect_tx.shared.b64 _, [%0], %1;" :: "r"((uint32_t)(a)), "r"((uint32_t)(b)) : "memory")
#define MBARRIER_ARRIVE(a) \
    asm volatile("mbarrier.arrive.shared.b64 _, [%0];" :: "r"((uint32_t)(a)) : "memory")

#define MBARRIER_WAIT_ACQ(a, ph) do {                                               \
    uint32_t _m = (uint32_t)(a), _p = (uint32_t)(ph), _d;                           \
    asm volatile("{\n\t.reg .pred p;\n\t"                                           \
        "mbarrier.try_wait.parity.acquire.cta.shared::cta.b64 p, [%1], %2;\n\t"     \
        "selp.b32 %0, 1, 0, p;\n\t}" : "=r"(_d) : "r"(_m), "r"(_p) : "memory");     \
    if (!_d) {                                                                       \
        asm volatile("{\n\t.reg .pred P1;\n\t"                                      \
            "WL_%=:\n\t"                                                            \
            "mbarrier.try_wait.parity.acquire.cta.shared::cta.b64 P1, [%0], %1, 0x989680;\n\t" \
            "@P1 bra.uni WD_%=;\n\t bra.uni WL_%=;\n\t WD_%=:\n\t}"                 \
            :: "r"(_m), "r"(_p) : "memory");                                        \
    }                                                                                \
} while (0)

#define MBARRIER_WAIT_RLX(a, ph) do {                                               \
    uint32_t _m = (uint32_t)(a), _p = (uint32_t)(ph), _d;                           \
    asm volatile("{\n\t.reg .pred p;\n\t"                                           \
        "mbarrier.try_wait.parity.relaxed.cta.shared::cta.b64 p, [%1], %2, 0x989680;\n\t" \
        "selp.b32 %0, 1, 0, p;\n\t}" : "=r"(_d) : "r"(_m), "r"(_p) : "memory");     \
    if (!_d) {                                                                       \
        asm volatile("{\n\t.reg .pred P1;\n\t"                                      \
            "WL_%=:\n\t"                                                            \
            "mbarrier.try_wait.parity.relaxed.cta.shared::cta.b64 P1, [%0], %1, 0x989680;\n\t" \
            "@P1 bra.uni WD_%=;\n\t bra.uni WL_%=;\n\t WD_%=:\n\t}"                 \
            :: "r"(_m), "r"(_p) : "memory");                                        \
    }                                                                                \
} while (0)

#define TMA_LOAD_2D(smem, map, c0, c1, mbar)                                        \
    asm volatile("cp.async.bulk.tensor.2d.shared::cta.global.tile.mbarrier::complete_tx::bytes " \
        "[%0], [%1, {%2, %3}], [%4];"                                               \
        :: "r"((uint32_t)(smem)), "l"(map), "r"((int)(c0)), "r"((int)(c1)),         \
           "r"((uint32_t)(mbar)) : "memory")

__device__ __forceinline__ void ldsm_x4(uint32_t r[4], uint32_t addr) {
    asm volatile("ldmatrix.sync.aligned.m8n8.x4.shared.b16 {%0,%1,%2,%3}, [%4];"
                 : "=r"(r[0]), "=r"(r[1]), "=r"(r[2]), "=r"(r[3]) : "r"(addr));
}
__device__ __forceinline__ void mma_f16(float c[4], const uint32_t a[4],
                                        uint32_t b0, uint32_t b1) {
    asm volatile(
        "mma.sync.aligned.m16n8k16.row.col.f32.f16.f16.f32 "
        "{%0,%1,%2,%3}, {%4,%5,%6,%7}, {%8,%9}, {%0,%1,%2,%3};"
        : "+f"(c[0]), "+f"(c[1]), "+f"(c[2]), "+f"(c[3])
        : "r"(a[0]), "r"(a[1]), "r"(a[2]), "r"(a[3]), "r"(b0), "r"(b1));
}

__global__ void __launch_bounds__(256) cvt_f16_kernel(
    const float4* __restrict__ in, __half2* __restrict__ out, int n4)
{
    int stride = gridDim.x * blockDim.x;
    for (int i = blockIdx.x * blockDim.x + threadIdx.x; i < n4; i += stride) {
        float4 v = in[i];
        out[2 * i]     = __floats2half2_rn(v.x, v.y);
        out[2 * i + 1] = __floats2half2_rn(v.z, v.w);
    }
}

extern __shared__ char smemc[];

// smem barriers: full[s] = sb + 16*s, empty[s] = sb + 16*s + 8
__global__ void __launch_bounds__(NTHREADS, 1) agg_gemm_kernel(
    const __grid_constant__ CUtensorMap tma_a,
    const __grid_constant__ CUtensorMap tma_b,
    float* __restrict__ out)
{
    const int t = threadIdx.x;
    const int wid = t >> 5;
    const int lane = t & 31;
    const int wm = wid & 3;          // warp M (0..3): 32 rows
    const int wn = wid >> 2;         // warp N (0..3): 64 cols
    const int g = lane >> 2;
    const int tig = lane & 3;

    const int m0 = blockIdx.y * BM;
    const int n0 = blockIdx.x * BN;

    const uint32_t sb = smem_u32(smemc);
    const uint32_t tiles = sb + SMEM_TILE_OFF;

    if (t == 0) {
        #pragma unroll
        for (int s = 0; s < STAGES; s++) {
            MBARRIER_INIT(sb + 16 * s, 1);           // full: tx-based
            MBARRIER_INIT(sb + 16 * s + 8, NWARPS);  // empty: 16 warp arrives
        }
    }
    __syncthreads();

    int pstage = 0, pphase = 1;      // producer cursor
    auto produce = [&](int chunk) {
        const uint32_t fullb = sb + 16 * pstage;
        MBARRIER_WAIT_RLX(fullb + 8, pphase);
        MBARRIER_EXPECT_TX(fullb, STAGE_BYTES);
        const uint32_t sbase = tiles + (uint32_t)pstage * STAGE_BYTES;
        TMA_LOAD_2D(sbase,                 &tma_a, chunk * BK, m0, fullb);
        TMA_LOAD_2D(sbase + A_STAGE_BYTES, &tma_b, chunk * BK, n0, fullb);
        if (++pstage == STAGES) { pstage = 0; pphase ^= 1; }
    };

    if (t == 0) {
        #pragma unroll
        for (int ps = 0; ps < STAGES - 1; ps++) produce(ps);
    }

    float acc[2][8][4];
    #pragma unroll
    for (int mi = 0; mi < 2; mi++)
        #pragma unroll
        for (int ni = 0; ni < 8; ni++)
            #pragma unroll
            for (int q = 0; q < 4; q++) acc[mi][ni][q] = 0.0f;

    // ldmatrix: row = base + (lane&15); chunk16 ^= (row & 7)
    const int lrow = lane & 15;
    const int lhi = lane >> 4;
    const int lsw = lane & 7;
    const uint32_t a_row_off = (uint32_t)(wm * 32 + lrow) * 128u;
    const uint32_t b_row_off = (uint32_t)A_STAGE_BYTES + (uint32_t)(wn * 64 + lrow) * 128u;

    int cstage = 0, cphase = 0;

    for (int c = 0; c < NCHUNK; c++) {
        const int fetch = c + STAGES - 1;
        if (t == 0 && fetch < NCHUNK) produce(fetch);

        const uint32_t fullb = sb + 16 * cstage;
        MBARRIER_WAIT_ACQ(fullb, cphase);

        const uint32_t sbase = tiles + (uint32_t)cstage * STAGE_BYTES;

        #pragma unroll
        for (int ks = 0; ks < 4; ks++) {
            const uint32_t chunk = (uint32_t)(((ks * 2 + lhi) ^ lsw) * 16);
            uint32_t a[2][4];
            #pragma unroll
            for (int mi = 0; mi < 2; mi++)
                ldsm_x4(a[mi], sbase + a_row_off + (uint32_t)(mi * 16 * 128) + chunk);
            uint32_t b[4][4];
            #pragma unroll
            for (int p = 0; p < 4; p++)
                ldsm_x4(b[p], sbase + b_row_off + (uint32_t)(p * 16 * 128) + chunk);
            #pragma unroll
            for (int mi = 0; mi < 2; mi++) {
                #pragma unroll
                for (int p = 0; p < 4; p++) {
                    mma_f16(acc[mi][2 * p],     a[mi], b[p][0], b[p][2]);
                    mma_f16(acc[mi][2 * p + 1], a[mi], b[p][1], b[p][3]);
                }
            }
        }

        if (lane == 0) MBARRIER_ARRIVE(fullb + 8);
        if (++cstage == STAGES) { cstage = 0; cphase ^= 1; }
    }

    // ---------------- epilogue ----------------
    #pragma unroll
    for (int mi = 0; mi < 2; mi++) {
        const int row = m0 + wm * 32 + mi * 16 + g;
        #pragma unroll
        for (int ni = 0; ni < 8; ni++) {
            const int col = n0 + wn * 64 + ni * 8 + 2 * tig;
            float2 lo = make_float2(acc[mi][ni][0], acc[mi][ni][1]);
            float2 hi = make_float2(acc[mi][ni][2], acc[mi][ni][3]);
            *reinterpret_cast<float2*>(out + (size_t)row * N_DIM + col) = lo;
            *reinterpret_cast<float2*>(out + (size_t)(row + 8) * N_DIM + col) = hi;
        }
    }
}

// ---------------- host ----------------
typedef CUresult (*PFN_EncodeTiled)(
    CUtensorMap*, CUtensorMapDataType, cuuint32_t, void*,
    const cuuint64_t*, const cuuint64_t*, const cuuint32_t*, const cuuint32_t*,
    CUtensorMapInterleave, CUtensorMapSwizzle, CUtensorMapL2promotion, CUtensorMapFloatOOBfill);

static void encode_2d_f16(PFN_EncodeTiled enc, CUtensorMap* map, void* ptr,
                          uint64_t dim0, uint64_t dim1, uint32_t box0, uint32_t box1) {
    cuuint64_t dims[2]    = {dim0, dim1};
    cuuint64_t strides[1] = {dim0 * sizeof(__half)};
    cuuint32_t box[2]     = {box0, box1};
    cuuint32_t estr[2]    = {1, 1};
    enc(map, CU_TENSOR_MAP_DATA_TYPE_FLOAT16, 2, ptr, dims, strides, box, estr,
        CU_TENSOR_MAP_INTERLEAVE_NONE, CU_TENSOR_MAP_SWIZZLE_128B,
        CU_TENSOR_MAP_L2_PROMOTION_L2_128B, CU_TENSOR_MAP_FLOAT_OOB_FILL_NONE);
}

extern "C" void kernel_launch(void* const* d_in, const int* in_sizes, int n_in,
                              void* d_out, int out_size) {
    const float* A_in = (const float*)d_in[0];   // [8,1024,4096] = [8192,4096]
    const float* W_in = (const float*)d_in[1];   // [4096,4096] K-major
    float* out = (float*)d_out;

    void *pA = nullptr, *pB = nullptr;
    cudaGetSymbolAddress(&pA, g_A);
    cudaGetSymbolAddress(&pB, g_B);

    void* fn = nullptr;
    cudaDriverEntryPointQueryResult st;
    cudaGetDriverEntryPointByVersion("cuTensorMapEncodeTiled", &fn, 12000,
                                     cudaEnableDefault, &st);
    PFN_EncodeTiled enc = (PFN_EncodeTiled)fn;

    CUtensorMap mapA, mapB;
    encode_2d_f16(enc, &mapA, pA, K_DIM, M_DIM, BK, BM);
    encode_2d_f16(enc, &mapB, pB, K_DIM, N_DIM, BK, BN);

    cudaFuncSetAttribute(agg_gemm_kernel,
                         cudaFuncAttributeMaxDynamicSharedMemorySize, SMEM_BYTES);

    cvt_f16_kernel<<<1184, 256>>>((const float4*)A_in, (__half2*)pA,
                                  (int)(((size_t)M_DIM * K_DIM) / 4));
    cvt_f16_kernel<<<1184, 256>>>((const float4*)W_in, (__half2*)pB,
                                  (int)(((size_t)N_DIM * K_DIM) / 4));

    dim3 grid(N_DIM / BN, M_DIM / BM);   // (16, 64)
    agg_gemm_kernel<<<grid, NTHREADS, SMEM_BYTES>>>(mapA, mapB, out);
}

// round 11
// speedup vs baseline: 1.0516x; 1.0059x over previous
#include <cuda_runtime.h>
#include <cuda.h>
#include <cuda_fp16.h>
#include <cstdint>

// ================================================================
// out[8192,4096] = A[8192,4096] (K-major) * W[4096,4096] (K-major)^T
// fp16 mma.sync m16n8k16 + ldmatrix + TMA (SW128), 4-stage
// producer/consumer mbarrier pipeline. CTA 128x256, 512 threads,
// warp tile 32x64. ks-rotation per warp + rotating producer warp.
// ================================================================

#define M_DIM 8192
#define N_DIM 4096
#define K_DIM 4096

#define BM 128
#define BN 256
#define BK 64                        // fp16 per K chunk = 128 B/row
#define STAGES 4
#define NCHUNK (K_DIM / BK)          // 64
#define NTHREADS 512
#define NWARPS 16

#define A_STAGE_BYTES (BM * 128)     // 16384
#define B_STAGE_BYTES (BN * 128)     // 32768
#define STAGE_BYTES   (A_STAGE_BYTES + B_STAGE_BYTES)      // 49152
#define SMEM_TILE_OFF 1024
#define SMEM_BYTES    (SMEM_TILE_OFF + STAGES * STAGE_BYTES)  // 197632

__device__ __align__(1024) __half g_A[(size_t)M_DIM * K_DIM];
__device__ __align__(1024) __half g_B[(size_t)N_DIM * K_DIM];

__device__ __forceinline__ uint32_t smem_u32(const void* p) {
    uint32_t a;
    asm("{ .reg .u64 t; cvta.to.shared.u64 t, %1; cvt.u32.u64 %0, t; }" : "=r"(a) : "l"(p));
    return a;
}
#define MBARRIER_INIT(a, n) \
    asm volatile("mbarrier.init.shared.b64 [%0], %1;" :: "r"((uint32_t)(a)), "r"((uint32_t)(n)) : "memory")
#define MBARRIER_EXPECT_TX(a, b) \
    asm volatile("mbarrier.arrive.expect_tx.shared.b64 _, [%0], %1;" :: "r"((uint32_t)(a)), "r"((uint32_t)(b)) : "memory")
#define MBARRIER_ARRIVE(a) \
    asm volatile("mbarrier.arrive.shared.b64 _, [%0];" :: "r"((uint32_t)(a)) : "memory")

#define MBARRIER_WAIT_ACQ(a, ph) do {                                               \
    uint32_t _m = (uint32_t)(a), _p = (uint32_t)(ph), _d;                           \
    asm volatile("{\n\t.reg .pred p;\n\t"                                           \
        "mbarrier.try_wait.parity.acquire.cta.shared::cta.b64 p, [%1], %2;\n\t"     \
        "selp.b32 %0, 1, 0, p;\n\t}" : "=r"(_d) : "r"(_m), "r"(_p) : "memory");     \
    if (!_d) {                                                                       \
        asm volatile("{\n\t.reg .pred P1;\n\t"                                      \
            "WL_%=:\n\t"                                                            \
            "mbarrier.try_wait.parity.acquire.cta.shared::cta.b64 P1, [%0], %1, 0x989680;\n\t" \
            "@P1 bra.uni WD_%=;\n\t bra.uni WL_%=;\n\t WD_%=:\n\t}"                 \
            :: "r"(_m), "r"(_p) : "memory");                                        \
    }                                                                                \
} while (0)

#define MBARRIER_WAIT_RLX(a, ph) do {                                               \
    uint32_t _m = (uint32_t)(a), _p = (uint32_t)(ph), _d;                           \
    asm volatile("{\n\t.reg .pred p;\n\t"                                           \
        "mbarrier.try_wait.parity.relaxed.cta.shared::cta.b64 p, [%1], %2, 0x989680;\n\t" \
        "selp.b32 %0, 1, 0, p;\n\t}" : "=r"(_d) : "r"(_m), "r"(_p) : "memory");     \
    if (!_d) {                                                                       \
        asm volatile("{\n\t.reg .pred P1;\n\t"                                      \
            "WL_%=:\n\t"                                                            \
            "mbarrier.try_wait.parity.relaxed.cta.shared::cta.b64 P1, [%0], %1, 0x989680;\n\t" \
            "@P1 bra.uni WD_%=;\n\t bra.uni WL_%=;\n\t WD_%=:\n\t}"                 \
            :: "r"(_m), "r"(_p) : "memory");                                        \
    }                                                                                \
} while (0)

#define TMA_LOAD_2D(smem, map, c0, c1, mbar)                                        \
    asm volatile("cp.async.bulk.tensor.2d.shared::cta.global.tile.mbarrier::complete_tx::bytes " \
        "[%0], [%1, {%2, %3}], [%4];"                                               \
        :: "r"((uint32_t)(smem)), "l"(map), "r"((int)(c0)), "r"((int)(c1)),         \
           "r"((uint32_t)(mbar)) : "memory")

__device__ __forceinline__ void ldsm_x4(uint32_t r[4], uint32_t addr) {
    asm volatile("ldmatrix.sync.aligned.m8n8.x4.shared.b16 {%0,%1,%2,%3}, [%4];"
                 : "=r"(r[0]), "=r"(r[1]), "=r"(r[2]), "=r"(r[3]) : "r"(addr));
}
__device__ __forceinline__ void mma_f16(float c[4], const uint32_t a[4],
                                        uint32_t b0, uint32_t b1) {
    asm volatile(
        "mma.sync.aligned.m16n8k16.row.col.f32.f16.f16.f32 "
        "{%0,%1,%2,%3}, {%4,%5,%6,%7}, {%8,%9}, {%0,%1,%2,%3};"
        : "+f"(c[0]), "+f"(c[1]), "+f"(c[2]), "+f"(c[3])
        : "r"(a[0]), "r"(a[1]), "r"(a[2]), "r"(a[3]), "r"(b0), "r"(b1));
}

__global__ void __launch_bounds__(256) cvt_f16_kernel(
    const float4* __restrict__ in, __half2* __restrict__ out, int n4)
{
    int stride = gridDim.x * blockDim.x;
    for (int i = blockIdx.x * blockDim.x + threadIdx.x; i < n4; i += stride) {
        float4 v = in[i];
        out[2 * i]     = __floats2half2_rn(v.x, v.y);
        out[2 * i + 1] = __floats2half2_rn(v.z, v.w);
    }
}

extern __shared__ char smemc[];

// smem barriers: full[s] = sb + 16*s, empty[s] = sb + 16*s + 8
__global__ void __launch_bounds__(NTHREADS, 1) agg_gemm_kernel(
    const __grid_constant__ CUtensorMap tma_a,
    const __grid_constant__ CUtensorMap tma_b,
    float* __restrict__ out)
{
    const int t = threadIdx.x;
    const int wid = t >> 5;
    const int lane = t & 31;
    const int wm = wid & 3;          // warp M (0..3): 32 rows
    const int wn = wid >> 2;         // warp N (0..3): 64 cols
    const int g = lane >> 2;
    const int tig = lane & 3;

    const int m0 = blockIdx.y * BM;
    const int n0 = blockIdx.x * BN;

    const uint32_t sb = smem_u32(smemc);
    const uint32_t tiles = sb + SMEM_TILE_OFF;

    if (t == 0) {
        #pragma unroll
        for (int s = 0; s < STAGES; s++) {
            MBARRIER_INIT(sb + 16 * s, 1);           // full: tx-based
            MBARRIER_INIT(sb + 16 * s + 8, NWARPS);  // empty: 16 warp arrives
        }
    }
    __syncthreads();

    // produce chunk f: stage = f % STAGES, empty-wait parity = 1 ^ ((f/STAGES)&1)
    auto produce = [&](int f) {
        const int st = f & (STAGES - 1);
        const int ph = 1 ^ ((f >> 2) & 1);
        const uint32_t fullb = sb + 16 * st;
        MBARRIER_WAIT_RLX(fullb + 8, ph);
        MBARRIER_EXPECT_TX(fullb, STAGE_BYTES);
        const uint32_t sbase = tiles + (uint32_t)st * STAGE_BYTES;
        TMA_LOAD_2D(sbase,                 &tma_a, f * BK, m0, fullb);
        TMA_LOAD_2D(sbase + A_STAGE_BYTES, &tma_b, f * BK, n0, fullb);
    };

    if (t == 0) {
        #pragma unroll
        for (int ps = 0; ps < STAGES - 1; ps++) produce(ps);
    }

    float acc[2][8][4];
    #pragma unroll
    for (int mi = 0; mi < 2; mi++)
        #pragma unroll
        for (int ni = 0; ni < 8; ni++)
            #pragma unroll
            for (int q = 0; q < 4; q++) acc[mi][ni][q] = 0.0f;

    // ldmatrix: row = base + (lane&15); chunk16 ^= (row & 7)
    const int lrow = lane & 15;
    const int lhi = lane >> 4;
    const int lsw = lane & 7;
    const uint32_t a_row_off = (uint32_t)(wm * 32 + lrow) * 128u;
    const uint32_t b_row_off = (uint32_t)A_STAGE_BYTES + (uint32_t)(wn * 64 + lrow) * 128u;

    const int ks0 = wid & 3;         // ks rotation start per warp

    int cstage = 0, cphase = 0;

    for (int c = 0; c < NCHUNK; c++) {
        // rotating producer: warp (fetch & 15) issues the TMA for chunk fetch
        const int fetch = c + STAGES - 1;
        if (fetch < NCHUNK && wid == (fetch & 15) && lane == 0) produce(fetch);

        const uint32_t fullb = sb + 16 * cstage;
        MBARRIER_WAIT_ACQ(fullb, cphase);

        const uint32_t sbase = tiles + (uint32_t)cstage * STAGE_BYTES;

        #pragma unroll
        for (int kk = 0; kk < 4; kk++) {
            const int ks = (ks0 + kk) & 3;
            const uint32_t chunk = (uint32_t)(((ks * 2 + lhi) ^ lsw) * 16);
            uint32_t a[2][4];
            #pragma unroll
            for (int mi = 0; mi < 2; mi++)
                ldsm_x4(a[mi], sbase + a_row_off + (uint32_t)(mi * 16 * 128) + chunk);
            uint32_t b[4][4];
            #pragma unroll
            for (int p = 0; p < 4; p++)
                ldsm_x4(b[p], sbase + b_row_off + (uint32_t)(p * 16 * 128) + chunk);
            #pragma unroll
            for (int mi = 0; mi < 2; mi++) {
                #pragma unroll
                for (int p = 0; p < 4; p++) {
                    mma_f16(acc[mi][2 * p],     a[mi], b[p][0], b[p][2]);
                    mma_f16(acc[mi][2 * p + 1], a[mi], b[p][1], b[p][3]);
                }
            }
        }

        if (lane == 0) MBARRIER_ARRIVE(fullb + 8);
        if (++cstage == STAGES) { cstage = 0; cphase ^= 1; }
    }

    // ---------------- epilogue ----------------
    #pragma unroll
    for (int mi = 0; mi < 2; mi++) {
        const int row = m0 + wm * 32 + mi * 16 + g;
        #pragma unroll
        for (int ni = 0; ni < 8; ni++) {
            const int col = n0 + wn * 64 + ni * 8 + 2 * tig;
            float2 lo = make_float2(acc[mi][ni][0], acc[mi][ni][1]);
            float2 hi = make_float2(acc[mi][ni][2], acc[mi][ni][3]);
            *reinterpret_cast<float2*>(out + (size_t)row * N_DIM + col) = lo;
            *reinterpret_cast<float2*>(out + (size_t)(row + 8) * N_DIM + col) = hi;
        }
    }
}

// ---------------- host ----------------
typedef CUresult (*PFN_EncodeTiled)(
    CUtensorMap*, CUtensorMapDataType, cuuint32_t, void*,
    const cuuint64_t*, const cuuint64_t*, const cuuint32_t*, const cuuint32_t*,
    CUtensorMapInterleave, CUtensorMapSwizzle, CUtensorMapL2promotion, CUtensorMapFloatOOBfill);

static void encode_2d_f16(PFN_EncodeTiled enc, CUtensorMap* map, void* ptr,
                          uint64_t dim0, uint64_t dim1, uint32_t box0, uint32_t box1) {
    cuuint64_t dims[2]    = {dim0, dim1};
    cuuint64_t strides[1] = {dim0 * sizeof(__half)};
    cuuint32_t box[2]     = {box0, box1};
    cuuint32_t estr[2]    = {1, 1};
    enc(map, CU_TENSOR_MAP_DATA_TYPE_FLOAT16, 2, ptr, dims, strides, box, estr,
        CU_TENSOR_MAP_INTERLEAVE_NONE, CU_TENSOR_MAP_SWIZZLE_128B,
        CU_TENSOR_MAP_L2_PROMOTION_L2_128B, CU_TENSOR_MAP_FLOAT_OOB_FILL_NONE);
}

extern "C" void kernel_launch(void* const* d_in, const int* in_sizes, int n_in,
                              void* d_out, int out_size) {
    const float* A_in = (const float*)d_in[0];   // [8,1024,4096] = [8192,4096]
    const float* W_in = (const float*)d_in[1];   // [4096,4096] K-major
    float* out = (float*)d_out;

    void *pA = nullptr, *pB = nullptr;
    cudaGetSymbolAddress(&pA, g_A);
    cudaGetSymbolAddress(&pB, g_B);

    void* fn = nullptr;
    cudaDriverEntryPointQueryResult st;
    cudaGetDriverEntryPointByVersion("cuTensorMapEncodeTiled", &fn, 12000,
                                     cudaEnableDefault, &st);
    PFN_EncodeTiled enc = (PFN_EncodeTiled)fn;

    CUtensorMap mapA, mapB;
    encode_2d_f16(enc, &mapA, pA, K_DIM, M_DIM, BK, BM);
    encode_2d_f16(enc, &mapB, pB, K_DIM, N_DIM, BK, BN);

    cudaFuncSetAttribute(agg_gemm_kernel,
                         cudaFuncAttributeMaxDynamicSharedMemorySize, SMEM_BYTES);

    cvt_f16_kernel<<<1184, 256>>>((const float4*)A_in, (__half2*)pA,
                                  (int)(((size_t)M_DIM * K_DIM) / 4));
    cvt_f16_kernel<<<1184, 256>>>((const float4*)W_in, (__half2*)pB,
                                  (int)(((size_t)N_DIM * K_DIM) / 4));

    dim3 grid(N_DIM / BN, M_DIM / BM);   // (16, 64)
    agg_gemm_kernel<<<grid, NTHREADS, SMEM_BYTES>>>(mapA, mapB, out);
}

// round 12
// speedup vs baseline: 1.0613x; 1.0093x over previous
#include <cuda_runtime.h>
#include <cuda.h>
#include <cuda_fp16.h>
#include <cstdint>

// ================================================================
// out[8192,4096] = A[8192,4096] (K-major) * W[4096,4096] (K-major)^T
// fp16 mma.sync m16n8k16 + ldmatrix + TMA (SW128), BK=128 chunks,
// 2-stage (96KB) producer/consumer mbarrier pipeline. CTA 128x256,
// 512 threads, warp tile 32x64, ks rotation, rotating producer.
// Fused single-kernel fp16 pre-pass.
// ================================================================

#define M_DIM 8192
#define N_DIM 4096
#define K_DIM 4096

#define BM 128
#define BN 256
#define BK 128                       // fp16 per K chunk (2 x 64-col panels)
#define STAGES 2
#define NCHUNK (K_DIM / BK)          // 32
#define NTHREADS 512
#define NWARPS 16

#define A_PANEL 16384                // 128 rows x 128B
#define B_PANEL 32768                // 256 rows x 128B
#define A_BYTES (2 * A_PANEL)        // 32768
#define B_OFF   A_BYTES
#define STAGE_BYTES (A_BYTES + 2 * B_PANEL)    // 98304
#define SMEM_TILE_OFF 1024
#define SMEM_BYTES (SMEM_TILE_OFF + STAGES * STAGE_BYTES)  // 197632

__device__ __align__(1024) __half g_A[(size_t)M_DIM * K_DIM];
__device__ __align__(1024) __half g_B[(size_t)N_DIM * K_DIM];

__device__ __forceinline__ uint32_t smem_u32(const void* p) {
    uint32_t a;
    asm("{ .reg .u64 t; cvta.to.shared.u64 t, %1; cvt.u32.u64 %0, t; }" : "=r"(a) : "l"(p));
    return a;
}
#define MBARRIER_INIT(a, n) \
    asm volatile("mbarrier.init.shared.b64 [%0], %1;" :: "r"((uint32_t)(a)), "r"((uint32_t)(n)) : "memory")
#define MBARRIER_EXPECT_TX(a, b) \
    asm volatile("mbarrier.arrive.expect_tx.shared.b64 _, [%0], %1;" :: "r"((uint32_t)(a)), "r"((uint32_t)(b)) : "memory")
#define MBARRIER_ARRIVE(a) \
    asm volatile("mbarrier.arrive.shared.b64 _, [%0];" :: "r"((uint32_t)(a)) : "memory")

#define MBARRIER_WAIT_ACQ(a, ph) do {                                               \
    uint32_t _m = (uint32_t)(a), _p = (uint32_t)(ph), _d;                           \
    asm volatile("{\n\t.reg .pred p;\n\t"                                           \
        "mbarrier.try_wait.parity.acquire.cta.shared::cta.b64 p, [%1], %2;\n\t"     \
        "selp.b32 %0, 1, 0, p;\n\t}" : "=r"(_d) : "r"(_m), "r"(_p) : "memory");     \
    if (!_d) {                                                                       \
        asm volatile("{\n\t.reg .pred P1;\n\t"                                      \
            "WL_%=:\n\t"                                                            \
            "mbarrier.try_wait.parity.acquire.cta.shared::cta.b64 P1, [%0], %1, 0x989680;\n\t" \
            "@P1 bra.uni WD_%=;\n\t bra.uni WL_%=;\n\t WD_%=:\n\t}"                 \
            :: "r"(_m), "r"(_p) : "memory");                                        \
    }                                                                                \
} while (0)

#define MBARRIER_WAIT_RLX(a, ph) do {                                               \
    uint32_t _m = (uint32_t)(a), _p = (uint32_t)(ph), _d;                           \
    asm volatile("{\n\t.reg .pred p;\n\t"                                           \
        "mbarrier.try_wait.parity.relaxed.cta.shared::cta.b64 p, [%1], %2, 0x989680;\n\t" \
        "selp.b32 %0, 1, 0, p;\n\t}" : "=r"(_d) : "r"(_m), "r"(_p) : "memory");     \
    if (!_d) {                                                                       \
        asm volatile("{\n\t.reg .pred P1;\n\t"                                      \
            "WL_%=:\n\t"                                                            \
            "mbarrier.try_wait.parity.relaxed.cta.shared::cta.b64 P1, [%0], %1, 0x989680;\n\t" \
            "@P1 bra.uni WD_%=;\n\t bra.uni WL_%=;\n\t WD_%=:\n\t}"                 \
            :: "r"(_m), "r"(_p) : "memory");                                        \
    }                                                                                \
} while (0)

#define TMA_LOAD_2D(smem, map, c0, c1, mbar)                                        \
    asm volatile("cp.async.bulk.tensor.2d.shared::cta.global.tile.mbarrier::complete_tx::bytes " \
        "[%0], [%1, {%2, %3}], [%4];"                                               \
        :: "r"((uint32_t)(smem)), "l"(map), "r"((int)(c0)), "r"((int)(c1)),         \
           "r"((uint32_t)(mbar)) : "memory")

__device__ __forceinline__ void ldsm_x4(uint32_t r[4], uint32_t addr) {
    asm volatile("ldmatrix.sync.aligned.m8n8.x4.shared.b16 {%0,%1,%2,%3}, [%4];"
                 : "=r"(r[0]), "=r"(r[1]), "=r"(r[2]), "=r"(r[3]) : "r"(addr));
}
__device__ __forceinline__ void mma_f16(float c[4], const uint32_t a[4],
                                        uint32_t b0, uint32_t b1) {
    asm volatile(
        "mma.sync.aligned.m16n8k16.row.col.f32.f16.f16.f32 "
        "{%0,%1,%2,%3}, {%4,%5,%6,%7}, {%8,%9}, {%0,%1,%2,%3};"
        : "+f"(c[0]), "+f"(c[1]), "+f"(c[2]), "+f"(c[3])
        : "r"(a[0]), "r"(a[1]), "r"(a[2]), "r"(a[3]), "r"(b0), "r"(b1));
}

// ---------------- fused pre-pass: fp32 -> fp16 for A and W ----------------
__global__ void __launch_bounds__(256) cvt_f16_fused(
    const float4* __restrict__ inA, const float4* __restrict__ inW,
    __half2* __restrict__ outA, __half2* __restrict__ outW,
    int n4A, int n4T)
{
    int stride = gridDim.x * blockDim.x;
    for (int i = blockIdx.x * blockDim.x + threadIdx.x; i < n4T; i += stride) {
        if (i < n4A) {
            float4 v = inA[i];
            outA[2 * i]     = __floats2half2_rn(v.x, v.y);
            outA[2 * i + 1] = __floats2half2_rn(v.z, v.w);
        } else {
            int j = i - n4A;
            float4 v = inW[j];
            outW[2 * j]     = __floats2half2_rn(v.x, v.y);
            outW[2 * j + 1] = __floats2half2_rn(v.z, v.w);
        }
    }
}

extern __shared__ char smemc[];

// smem barriers: full[s] = sb + 16*s, empty[s] = sb + 16*s + 8
__global__ void __launch_bounds__(NTHREADS, 1) agg_gemm_kernel(
    const __grid_constant__ CUtensorMap tma_a,
    const __grid_constant__ CUtensorMap tma_b,
    float* __restrict__ out)
{
    const int t = threadIdx.x;
    const int wid = t >> 5;
    const int lane = t & 31;
    const int wm = wid & 3;          // warp M (0..3): 32 rows
    const int wn = wid >> 2;         // warp N (0..3): 64 cols
    const int g = lane >> 2;
    const int tig = lane & 3;

    const int m0 = blockIdx.y * BM;
    const int n0 = blockIdx.x * BN;

    const uint32_t sb = smem_u32(smemc);
    const uint32_t tiles = sb + SMEM_TILE_OFF;

    if (t == 0) {
        #pragma unroll
        for (int s = 0; s < STAGES; s++) {
            MBARRIER_INIT(sb + 16 * s, 1);           // full: tx-based
            MBARRIER_INIT(sb + 16 * s + 8, NWARPS);  // empty: 16 warp arrives
        }
    }
    __syncthreads();

    // produce chunk f -> stage f&1, empty parity 1 ^ ((f>>1)&1)
    auto produce = [&](int f) {
        const int st = f & (STAGES - 1);
        const int ph = 1 ^ ((f >> 1) & 1);
        const uint32_t fullb = sb + 16 * st;
        MBARRIER_WAIT_RLX(fullb + 8, ph);
        MBARRIER_EXPECT_TX(fullb, STAGE_BYTES);
        const uint32_t sbase = tiles + (uint32_t)st * STAGE_BYTES;
        const int k0 = f * BK;
        TMA_LOAD_2D(sbase,                     &tma_a, k0,      m0, fullb);
        TMA_LOAD_2D(sbase + A_PANEL,           &tma_a, k0 + 64, m0, fullb);
        TMA_LOAD_2D(sbase + B_OFF,             &tma_b, k0,      n0, fullb);
        TMA_LOAD_2D(sbase + B_OFF + B_PANEL,   &tma_b, k0 + 64, n0, fullb);
    };

    if (t == 0) produce(0);          // prologue: STAGES-1 = 1 chunk

    float acc[2][8][4];
    #pragma unroll
    for (int mi = 0; mi < 2; mi++)
        #pragma unroll
        for (int ni = 0; ni < 8; ni++)
            #pragma unroll
            for (int q = 0; q < 4; q++) acc[mi][ni][q] = 0.0f;

    // ldmatrix: row = base + (lane&15); within panel chunk16 ^= (row & 7)
    const int lrow = lane & 15;
    const int lhi = lane >> 4;
    const int lsw = lane & 7;
    const uint32_t a_row_off = (uint32_t)(wm * 32 + lrow) * 128u;
    const uint32_t b_row_off = (uint32_t)(wn * 64 + lrow) * 128u;

    const int ks0 = wid & 7;         // ks rotation start (8 slices per chunk)

    int cstage = 0, cphase = 0;

    for (int c = 0; c < NCHUNK; c++) {
        const int fetch = c + STAGES - 1;
        if (fetch < NCHUNK && wid == (fetch & 15) && lane == 0) produce(fetch);

        const uint32_t fullb = sb + 16 * cstage;
        MBARRIER_WAIT_ACQ(fullb, cphase);

        const uint32_t sbase = tiles + (uint32_t)cstage * STAGE_BYTES;

        #pragma unroll
        for (int kk = 0; kk < 8; kk++) {
            const int ks = (ks0 + kk) & 7;
            const int h = ks >> 2;               // panel (k-half)
            const int ksl = ks & 3;
            const uint32_t chunk = (uint32_t)(((ksl * 2 + lhi) ^ lsw) * 16);
            const uint32_t abase = sbase + (uint32_t)(h * A_PANEL) + a_row_off + chunk;
            const uint32_t bbase = sbase + B_OFF + (uint32_t)(h * B_PANEL) + b_row_off + chunk;
            uint32_t a[2][4];
            #pragma unroll
            for (int mi = 0; mi < 2; mi++)
                ldsm_x4(a[mi], abase + (uint32_t)(mi * 16 * 128));
            uint32_t b[4][4];
            #pragma unroll
            for (int p = 0; p < 4; p++)
                ldsm_x4(b[p], bbase + (uint32_t)(p * 16 * 128));
            #pragma unroll
            for (int mi = 0; mi < 2; mi++) {
                #pragma unroll
                for (int p = 0; p < 4; p++) {
                    mma_f16(acc[mi][2 * p],     a[mi], b[p][0], b[p][2]);
                    mma_f16(acc[mi][2 * p + 1], a[mi], b[p][1], b[p][3]);
                }
            }
        }

        if (lane == 0) MBARRIER_ARRIVE(fullb + 8);
        if (++cstage == STAGES) { cstage = 0; cphase ^= 1; }
    }

    // ---------------- epilogue ----------------
    #pragma unroll
    for (int mi = 0; mi < 2; mi++) {
        const int row = m0 + wm * 32 + mi * 16 + g;
        #pragma unroll
        for (int ni = 0; ni < 8; ni++) {
            const int col = n0 + wn * 64 + ni * 8 + 2 * tig;
            float2 lo = make_float2(acc[mi][ni][0], acc[mi][ni][1]);
            float2 hi = make_float2(acc[mi][ni][2], acc[mi][ni][3]);
            *reinterpret_cast<float2*>(out + (size_t)row * N_DIM + col) = lo;
            *reinterpret_cast<float2*>(out + (size_t)(row + 8) * N_DIM + col) = hi;
        }
    }
}

// ---------------- host ----------------
typedef CUresult (*PFN_EncodeTiled)(
    CUtensorMap*, CUtensorMapDataType, cuuint32_t, void*,
    const cuuint64_t*, const cuuint64_t*, const cuuint32_t*, const cuuint32_t*,
    CUtensorMapInterleave, CUtensorMapSwizzle, CUtensorMapL2promotion, CUtensorMapFloatOOBfill);

static void encode_2d_f16(PFN_EncodeTiled enc, CUtensorMap* map, void* ptr,
                          uint64_t dim0, uint64_t dim1, uint32_t box0, uint32_t box1) {
    cuuint64_t dims[2]    = {dim0, dim1};
    cuuint64_t strides[1] = {dim0 * sizeof(__half)};
    cuuint32_t box[2]     = {box0, box1};
    cuuint32_t estr[2]    = {1, 1};
    enc(map, CU_TENSOR_MAP_DATA_TYPE_FLOAT16, 2, ptr, dims, strides, box, estr,
        CU_TENSOR_MAP_INTERLEAVE_NONE, CU_TENSOR_MAP_SWIZZLE_128B,
        CU_TENSOR_MAP_L2_PROMOTION_L2_128B, CU_TENSOR_MAP_FLOAT_OOB_FILL_NONE);
}

extern "C" void kernel_launch(void* const* d_in, const int* in_sizes, int n_in,
                              void* d_out, int out_size) {
    const float* A_in = (const float*)d_in[0];   // [8,1024,4096] = [8192,4096]
    const float* W_in = (const float*)d_in[1];   // [4096,4096] K-major
    float* out = (float*)d_out;

    void *pA = nullptr, *pB = nullptr;
    cudaGetSymbolAddress(&pA, g_A);
    cudaGetSymbolAddress(&pB, g_B);

    void* fn = nullptr;
    cudaDriverEntryPointQueryResult st;
    cudaGetDriverEntryPointByVersion("cuTensorMapEncodeTiled", &fn, 12000,
                                     cudaEnableDefault, &st);
    PFN_EncodeTiled enc = (PFN_EncodeTiled)fn;

    CUtensorMap mapA, mapB;
    encode_2d_f16(enc, &mapA, pA, K_DIM, M_DIM, 64, BM);
    encode_2d_f16(enc, &mapB, pB, K_DIM, N_DIM, 64, BN);

    cudaFuncSetAttribute(agg_gemm_kernel,
                         cudaFuncAttributeMaxDynamicSharedMemorySize, SMEM_BYTES);

    const int n4A = (int)(((size_t)M_DIM * K_DIM) / 4);
    const int n4W = (int)(((size_t)N_DIM * K_DIM) / 4);
    cvt_f16_fused<<<2368, 256>>>((const float4*)A_in, (const float4*)W_in,
                                 (__half2*)pA, (__half2*)pB, n4A, n4A + n4W);

    dim3 grid(N_DIM / BN, M_DIM / BM);   // (16, 64)
    agg_gemm_kernel<<<grid, NTHREADS, SMEM_BYTES>>>(mapA, mapB, out);
}

// round 13
// speedup vs baseline: 1.0653x; 1.0037x over previous
#include <cuda_runtime.h>
#include <cuda.h>
#include <cuda_fp16.h>
#include <cstdint>

// ================================================================
// out[8192,4096] = A[8192,4096] (K-major) * W[4096,4096] (K-major)^T
// fp16 mma.sync m16n8k16 + ldmatrix + TMA (SW128), 4-stage
// producer/consumer mbarrier pipeline. CTA 128x256, 512 threads,
// warp tile 32x64, ks rotation, rotating producer, early
// empty-arrive after last LDSM. Fused fp16 pre-pass.
// ================================================================

#define M_DIM 8192
#define N_DIM 4096
#define K_DIM 4096

#define BM 128
#define BN 256
#define BK 64                        // fp16 per K chunk = 128 B/row
#define STAGES 4
#define NCHUNK (K_DIM / BK)          // 64
#define NTHREADS 512
#define NWARPS 16

#define A_STAGE_BYTES (BM * 128)     // 16384
#define B_STAGE_BYTES (BN * 128)     // 32768
#define STAGE_BYTES   (A_STAGE_BYTES + B_STAGE_BYTES)      // 49152
#define SMEM_TILE_OFF 1024
#define SMEM_BYTES    (SMEM_TILE_OFF + STAGES * STAGE_BYTES)  // 197632

__device__ __align__(1024) __half g_A[(size_t)M_DIM * K_DIM];
__device__ __align__(1024) __half g_B[(size_t)N_DIM * K_DIM];

__device__ __forceinline__ uint32_t smem_u32(const void* p) {
    uint32_t a;
    asm("{ .reg .u64 t; cvta.to.shared.u64 t, %1; cvt.u32.u64 %0, t; }" : "=r"(a) : "l"(p));
    return a;
}
#define MBARRIER_INIT(a, n) \
    asm volatile("mbarrier.init.shared.b64 [%0], %1;" :: "r"((uint32_t)(a)), "r"((uint32_t)(n)) : "memory")
#define MBARRIER_EXPECT_TX(a, b) \
    asm volatile("mbarrier.arrive.expect_tx.shared.b64 _, [%0], %1;" :: "r"((uint32_t)(a)), "r"((uint32_t)(b)) : "memory")
#define MBARRIER_ARRIVE(a) \
    asm volatile("mbarrier.arrive.shared.b64 _, [%0];" :: "r"((uint32_t)(a)) : "memory")

#define MBARRIER_WAIT_ACQ(a, ph) do {                                               \
    uint32_t _m = (uint32_t)(a), _p = (uint32_t)(ph), _d;                           \
    asm volatile("{\n\t.reg .pred p;\n\t"                                           \
        "mbarrier.try_wait.parity.acquire.cta.shared::cta.b64 p, [%1], %2;\n\t"     \
        "selp.b32 %0, 1, 0, p;\n\t}" : "=r"(_d) : "r"(_m), "r"(_p) : "memory");     \
    if (!_d) {                                                                       \
        asm volatile("{\n\t.reg .pred P1;\n\t"                                      \
            "WL_%=:\n\t"                                                            \
            "mbarrier.try_wait.parity.acquire.cta.shared::cta.b64 P1, [%0], %1, 0x989680;\n\t" \
            "@P1 bra.uni WD_%=;\n\t bra.uni WL_%=;\n\t WD_%=:\n\t}"                 \
            :: "r"(_m), "r"(_p) : "memory");                                        \
    }                                                                                \
} while (0)

#define MBARRIER_WAIT_RLX(a, ph) do {                                               \
    uint32_t _m = (uint32_t)(a), _p = (uint32_t)(ph), _d;                           \
    asm volatile("{\n\t.reg .pred p;\n\t"                                           \
        "mbarrier.try_wait.parity.relaxed.cta.shared::cta.b64 p, [%1], %2, 0x989680;\n\t" \
        "selp.b32 %0, 1, 0, p;\n\t}" : "=r"(_d) : "r"(_m), "r"(_p) : "memory");     \
    if (!_d) {                                                                       \
        asm volatile("{\n\t.reg .pred P1;\n\t"                                      \
            "WL_%=:\n\t"                                                            \
            "mbarrier.try_wait.parity.relaxed.cta.shared::cta.b64 P1, [%0], %1, 0x989680;\n\t" \
            "@P1 bra.uni WD_%=;\n\t bra.uni WL_%=;\n\t WD_%=:\n\t}"                 \
            :: "r"(_m), "r"(_p) : "memory");                                        \
    }                                                                                \
} while (0)

#define TMA_LOAD_2D(smem, map, c0, c1, mbar)                                        \
    asm volatile("cp.async.bulk.tensor.2d.shared::cta.global.tile.mbarrier::complete_tx::bytes " \
        "[%0], [%1, {%2, %3}], [%4];"                                               \
        :: "r"((uint32_t)(smem)), "l"(map), "r"((int)(c0)), "r"((int)(c1)),         \
           "r"((uint32_t)(mbar)) : "memory")

__device__ __forceinline__ void ldsm_x4(uint32_t r[4], uint32_t addr) {
    asm volatile("ldmatrix.sync.aligned.m8n8.x4.shared.b16 {%0,%1,%2,%3}, [%4];"
                 : "=r"(r[0]), "=r"(r[1]), "=r"(r[2]), "=r"(r[3]) : "r"(addr));
}
__device__ __forceinline__ void mma_f16(float c[4], const uint32_t a[4],
                                        uint32_t b0, uint32_t b1) {
    asm volatile(
        "mma.sync.aligned.m16n8k16.row.col.f32.f16.f16.f32 "
        "{%0,%1,%2,%3}, {%4,%5,%6,%7}, {%8,%9}, {%0,%1,%2,%3};"
        : "+f"(c[0]), "+f"(c[1]), "+f"(c[2]), "+f"(c[3])
        : "r"(a[0]), "r"(a[1]), "r"(a[2]), "r"(a[3]), "r"(b0), "r"(b1));
}

// ---------------- fused pre-pass: fp32 -> fp16 for A and W ----------------
__global__ void __launch_bounds__(256) cvt_f16_fused(
    const float4* __restrict__ inA, const float4* __restrict__ inW,
    __half2* __restrict__ outA, __half2* __restrict__ outW,
    int n4A, int n4T)
{
    int stride = gridDim.x * blockDim.x;
    for (int i = blockIdx.x * blockDim.x + threadIdx.x; i < n4T; i += stride) {
        if (i < n4A) {
            float4 v = inA[i];
            outA[2 * i]     = __floats2half2_rn(v.x, v.y);
            outA[2 * i + 1] = __floats2half2_rn(v.z, v.w);
        } else {
            int j = i - n4A;
            float4 v = inW[j];
            outW[2 * j]     = __floats2half2_rn(v.x, v.y);
            outW[2 * j + 1] = __floats2half2_rn(v.z, v.w);
        }
    }
}

extern __shared__ char smemc[];

// smem barriers: full[s] = sb + 16*s, empty[s] = sb + 16*s + 8
__global__ void __launch_bounds__(NTHREADS, 1) agg_gemm_kernel(
    const __grid_constant__ CUtensorMap tma_a,
    const __grid_constant__ CUtensorMap tma_b,
    float* __restrict__ out)
{
    const int t = threadIdx.x;
    const int wid = t >> 5;
    const int lane = t & 31;
    const int wm = wid & 3;          // warp M (0..3): 32 rows
    const int wn = wid >> 2;         // warp N (0..3): 64 cols
    const int g = lane >> 2;
    const int tig = lane & 3;

    const int m0 = blockIdx.y * BM;
    const int n0 = blockIdx.x * BN;

    const uint32_t sb = smem_u32(smemc);
    const uint32_t tiles = sb + SMEM_TILE_OFF;

    if (t == 0) {
        #pragma unroll
        for (int s = 0; s < STAGES; s++) {
            MBARRIER_INIT(sb + 16 * s, 1);           // full: tx-based
            MBARRIER_INIT(sb + 16 * s + 8, NWARPS);  // empty: 16 warp arrives
        }
    }
    __syncthreads();

    // produce chunk f: stage = f % STAGES, empty-wait parity = 1 ^ ((f/STAGES)&1)
    auto produce = [&](int f) {
        const int st = f & (STAGES - 1);
        const int ph = 1 ^ ((f >> 2) & 1);
        const uint32_t fullb = sb + 16 * st;
        MBARRIER_WAIT_RLX(fullb + 8, ph);
        MBARRIER_EXPECT_TX(fullb, STAGE_BYTES);
        const uint32_t sbase = tiles + (uint32_t)st * STAGE_BYTES;
        TMA_LOAD_2D(sbase,                 &tma_a, f * BK, m0, fullb);
        TMA_LOAD_2D(sbase + A_STAGE_BYTES, &tma_b, f * BK, n0, fullb);
    };

    if (t == 0) {
        #pragma unroll
        for (int ps = 0; ps < STAGES - 1; ps++) produce(ps);
    }

    float acc[2][8][4];
    #pragma unroll
    for (int mi = 0; mi < 2; mi++)
        #pragma unroll
        for (int ni = 0; ni < 8; ni++)
            #pragma unroll
            for (int q = 0; q < 4; q++) acc[mi][ni][q] = 0.0f;

    // ldmatrix: row = base + (lane&15); chunk16 ^= (row & 7)
    const int lrow = lane & 15;
    const int lhi = lane >> 4;
    const int lsw = lane & 7;
    const uint32_t a_row_off = (uint32_t)(wm * 32 + lrow) * 128u;
    const uint32_t b_row_off = (uint32_t)A_STAGE_BYTES + (uint32_t)(wn * 64 + lrow) * 128u;

    const int ks0 = wid & 3;         // ks rotation start per warp

    int cstage = 0, cphase = 0;

    for (int c = 0; c < NCHUNK; c++) {
        // rotating producer: warp (fetch & 15) issues the TMA for chunk fetch
        const int fetch = c + STAGES - 1;
        if (fetch < NCHUNK && wid == (fetch & 15) && lane == 0) produce(fetch);

        const uint32_t fullb = sb + 16 * cstage;
        MBARRIER_WAIT_ACQ(fullb, cphase);

        const uint32_t sbase = tiles + (uint32_t)cstage * STAGE_BYTES;

        #pragma unroll
        for (int kk = 0; kk < 4; kk++) {
            const int ks = (ks0 + kk) & 3;
            const uint32_t chunk = (uint32_t)(((ks * 2 + lhi) ^ lsw) * 16);
            uint32_t a[2][4];
            #pragma unroll
            for (int mi = 0; mi < 2; mi++)
                ldsm_x4(a[mi], sbase + a_row_off + (uint32_t)(mi * 16 * 128) + chunk);
            uint32_t b[4][4];
            #pragma unroll
            for (int p = 0; p < 4; p++)
                ldsm_x4(b[p], sbase + b_row_off + (uint32_t)(p * 16 * 128) + chunk);

            // after the final slice's LDSMs this warp is done READING the
            // stage -> release it before the trailing HMMAs
            if (kk == 3 && lane == 0) MBARRIER_ARRIVE(fullb + 8);

            #pragma unroll
            for (int mi = 0; mi < 2; mi++) {
                #pragma unroll
                for (int p = 0; p < 4; p++) {
                    mma_f16(acc[mi][2 * p],     a[mi], b[p][0], b[p][2]);
                    mma_f16(acc[mi][2 * p + 1], a[mi], b[p][1], b[p][3]);
                }
            }
        }

        if (++cstage == STAGES) { cstage = 0; cphase ^= 1; }
    }

    // ---------------- epilogue ----------------
    #pragma unroll
    for (int mi = 0; mi < 2; mi++) {
        const int row = m0 + wm * 32 + mi * 16 + g;
        #pragma unroll
        for (int ni = 0; ni < 8; ni++) {
            const int col = n0 + wn * 64 + ni * 8 + 2 * tig;
            float2 lo = make_float2(acc[mi][ni][0], acc[mi][ni][1]);
            float2 hi = make_float2(acc[mi][ni][2], acc[mi][ni][3]);
            *reinterpret_cast<float2*>(out + (size_t)row * N_DIM + col) = lo;
            *reinterpret_cast<float2*>(out + (size_t)(row + 8) * N_DIM + col) = hi;
        }
    }
}

// ---------------- host ----------------
typedef CUresult (*PFN_EncodeTiled)(
    CUtensorMap*, CUtensorMapDataType, cuuint32_t, void*,
    const cuuint64_t*, const cuuint64_t*, const cuuint32_t*, const cuuint32_t*,
    CUtensorMapInterleave, CUtensorMapSwizzle, CUtensorMapL2promotion, CUtensorMapFloatOOBfill);

static void encode_2d_f16(PFN_EncodeTiled enc, CUtensorMap* map, void* ptr,
                          uint64_t dim0, uint64_t dim1, uint32_t box0, uint32_t box1) {
    cuuint64_t dims[2]    = {dim0, dim1};
    cuuint64_t strides[1] = {dim0 * sizeof(__half)};
    cuuint32_t box[2]     = {box0, box1};
    cuuint32_t estr[2]    = {1, 1};
    enc(map, CU_TENSOR_MAP_DATA_TYPE_FLOAT16, 2, ptr, dims, strides, box, estr,
        CU_TENSOR_MAP_INTERLEAVE_NONE, CU_TENSOR_MAP_SWIZZLE_128B,
        CU_TENSOR_MAP_L2_PROMOTION_L2_128B, CU_TENSOR_MAP_FLOAT_OOB_FILL_NONE);
}

extern "C" void kernel_launch(void* const* d_in, const int* in_sizes, int n_in,
                              void* d_out, int out_size) {
    const float* A_in = (const float*)d_in[0];   // [8,1024,4096] = [8192,4096]
    const float* W_in = (const float*)d_in[1];   // [4096,4096] K-major
    float* out = (float*)d_out;

    void *pA = nullptr, *pB = nullptr;
    cudaGetSymbolAddress(&pA, g_A);
    cudaGetSymbolAddress(&pB, g_B);

    void* fn = nullptr;
    cudaDriverEntryPointQueryResult st;
    cudaGetDriverEntryPointByVersion("cuTensorMapEncodeTiled", &fn, 12000,
                                     cudaEnableDefault, &st);
    PFN_EncodeTiled enc = (PFN_EncodeTiled)fn;

    CUtensorMap mapA, mapB;
    encode_2d_f16(enc, &mapA, pA, K_DIM, M_DIM, BK, BM);
    encode_2d_f16(enc, &mapB, pB, K_DIM, N_DIM, BK, BN);

    cudaFuncSetAttribute(agg_gemm_kernel,
                         cudaFuncAttributeMaxDynamicSharedMemorySize, SMEM_BYTES);

    const int n4A = (int)(((size_t)M_DIM * K_DIM) / 4);
    const int n4W = (int)(((size_t)N_DIM * K_DIM) / 4);
    cvt_f16_fused<<<2368, 256>>>((const float4*)A_in, (const float4*)W_in,
                                 (__half2*)pA, (__half2*)pB, n4A, n4A + n4W);

    dim3 grid(N_DIM / BN, M_DIM / BM);   // (16, 64)
    agg_gemm_kernel<<<grid, NTHREADS, SMEM_BYTES>>>(mapA, mapB, out);
}